// round 7
// baseline (speedup 1.0000x reference)
#include <cuda_runtime.h>
#include <cstdint>

#define B 8
#define L 512
#define H 20
#define D 1280
#define K 32

#define MV_BLOCKS     320   // 16 warps * 320 = 5120 half-rows = 2*2560 rows
#define TOPK_BLOCKS   16    // 2 reps * 8 batches
#define BIAS_BLOCK    (MV_BLOCKS + TOPK_BLOCKS)          // 336
#define GATHER_BASE   (MV_BLOCKS + TOPK_BLOCKS + 1)      // 337
#define NB            (GATHER_BASE + 16)                 // 353

// Scratch (no allocations allowed in kernel_launch)
__device__ int   g_idx[2][B][K];    // top-K token indices per (rep, batch)
__device__ float g_up[2][4][D];     // j-half partials of u1,u2,v1,v2
__device__ float g_s[2][B][D];      // gather-SUM of selected rep rows
__device__ float g_bias;            // batch-independent bias dot
__device__ volatile int g_rb_done[2][B];  // per-(rep,batch) topk "done" seq flag
__device__ unsigned g_seq;          // replay sequence number (flags compare vs seq)

// ---------------------------------------------------------------------------
// Warp-register bitonic sort, 32 u64 keys across lanes, DESCENDING.
// ---------------------------------------------------------------------------
__device__ __forceinline__ unsigned long long warp_sort_desc(
    unsigned long long key, int lane)
{
    unsigned long long v = ~key;
#pragma unroll
    for (int k = 2; k <= 32; k <<= 1) {
#pragma unroll
        for (int j = k >> 1; j > 0; j >>= 1) {
            unsigned long long other = __shfl_xor_sync(0xffffffffu, v, j);
            bool lower = (lane & j) == 0;
            bool up    = (lane & k) == 0;
            unsigned long long mn = (v < other) ? v : other;
            unsigned long long mx = (v < other) ? other : v;
            v = (lower == up) ? mn : mx;
        }
    }
    return ~v;
}

__device__ __forceinline__ float dot4(float4 a, float4 b) {
    return a.x * b.x + a.y * b.y + a.z * b.z + a.w * b.w;
}
__device__ __forceinline__ float4 add4(float4 a, float4 b) {
    return make_float4(a.x + b.x, a.y + b.y, a.z + b.z, a.w + b.w);
}

// ---------------------------------------------------------------------------
// Kernel A. Block roles by blockIdx.x:
//   [0,320):   dual matvec half-rows (W read exactly once)     -> g_up
//   [320,336): top-K per (rep,batch), sets g_rb_done[r][b]     -> g_idx
//   336:       bias dot                                        -> g_bias
//   [337,353): gather-sum per (rep,batch), spins on own flag   -> g_s
// No global tail: kernel ends when slowest block ends.
// ---------------------------------------------------------------------------
__global__ void __launch_bounds__(512) k_A(
    const float* __restrict__ rep1, const float* __restrict__ rep2,
    const float* __restrict__ attn1, const float* __restrict__ attn2,
    const int* __restrict__ pos,
    const float* __restrict__ cls_W, const float* __restrict__ env_W,
    const float* __restrict__ cls_b, const float* __restrict__ env_b,
    const float* __restrict__ clsclf_W, const float* __restrict__ envclf_W,
    const float* __restrict__ cls_c1, const float* __restrict__ cls_c2,
    const float* __restrict__ env_c1, const float* __restrict__ env_c2)
{
    const int tid  = threadIdx.x;
    const int warp = tid >> 5;
    const int lane = tid & 31;

    if (blockIdx.x < MV_BLOCKS) {
        // ---- dual matvec: one warp per HALF row (640 floats) --------------
        const int gw   = blockIdx.x * 16 + warp;   // 0..5119
        const int half = gw & 1;
        const int grow = gw >> 1;                  // 0..2559
        const int mat  = grow >= D;
        const int row  = grow - mat * D;
        const float* W  = mat ? env_W    : cls_W;
        const float* wc = mat ? envclf_W : clsclf_W;
        const float* c1 = mat ? env_c1   : cls_c1;
        const float* c2 = mat ? env_c2   : cls_c2;
        const float* Wr = W + (size_t)row * D;
        const int j0 = half * (D / 2) + lane * 4;

        float4 wv[5];
#pragma unroll
        for (int it = 0; it < 5; ++it)
            wv[it] = *(const float4*)(Wr + j0 + it * 128);

        float a1 = 0.f, a2 = 0.f;
#pragma unroll
        for (int it = 0; it < 5; ++it) {
            const int j = j0 + it * 128;
            float4 wcv = *(const float4*)(wc + j);
            float4 c1v = *(const float4*)(c1 + j);
            float4 c2v = *(const float4*)(c2 + j);
            float sx = wv[it].x * wcv.x, sy = wv[it].y * wcv.y,
                  sz = wv[it].z * wcv.z, sw = wv[it].w * wcv.w;
            a1 += sx * c1v.x + sy * c1v.y + sz * c1v.z + sw * c1v.w;
            a2 += sx * c2v.x + sy * c2v.y + sz * c2v.z + sw * c2v.w;
        }
#pragma unroll
        for (int o = 16; o; o >>= 1) {
            a1 += __shfl_xor_sync(0xffffffffu, a1, o);
            a2 += __shfl_xor_sync(0xffffffffu, a2, o);
        }
        if (lane == 0) {
            g_up[half][mat * 2 + 0][row] = a1;
            g_up[half][mat * 2 + 1][row] = a2;
        }
    }
    else if (blockIdx.x < BIAS_BLOCK) {
        // ---- top-K for one (rep, batch) ------------------------------------
        const int tb = blockIdx.x - MV_BLOCKS;   // 0..15
        const int b  = tb & 7;
        const int r  = tb >> 3;
        const float* attn = r ? attn2 : attn1;
        const int l = tid;                       // token 0..511
        const int p = pos[b];

        const float* base = attn + ((size_t)b * H) * (size_t)(L * L)
                                 + (size_t)p * L + l;
        float s = 0.f;
#pragma unroll
        for (int h = 0; h < H; ++h)
            s += base[(size_t)h * (L * L)];

        unsigned fb = __float_as_uint(s * (1.0f / H));
        fb = (fb & 0x80000000u) ? ~fb : (fb | 0x80000000u);
        unsigned long long key =
            ((unsigned long long)fb << 32) | (unsigned)(L - 1 - l);

        key = warp_sort_desc(key, lane);

        __shared__ unsigned long long sorted[16][32];
        sorted[warp][lane] = key;
        __syncthreads();

        if (warp == 0) {
            unsigned long long h = (lane < 16) ? sorted[lane][0] : 0ull;
            int ptr = 0;
#pragma unroll
            for (int i = 0; i < K; ++i) {
                unsigned long long m = h;
#pragma unroll
                for (int o = 8; o; o >>= 1) {
                    unsigned long long other = __shfl_xor_sync(0xffffffffu, m, o);
                    if (other > m) m = other;
                }
                m = __shfl_sync(0xffffffffu, m, 0);
                if (h == m) {
                    g_idx[r][b][i] = L - 1 - (int)(m & 0xffffffffu);
                    ++ptr;
                    h = (ptr < 32) ? sorted[lane][ptr] : 0ull;
                }
            }
            __syncwarp();
            if (lane == 0) {
                __threadfence();
                // publish with the current replay sequence value
                g_rb_done[r][b] = (int)(g_seq + 1u);
            }
        }
    }
    else if (blockIdx.x == BIAS_BLOCK) {
        // ---- bias dot (one warp) -------------------------------------------
        if (warp == 0) {
            float a = 0.f;
            for (int d = lane; d < D; d += 32)
                a += cls_b[d] * (cls_c1[d] + cls_c2[d]) * clsclf_W[d]
                   + env_b[d] * (env_c1[d] + env_c2[d]) * envclf_W[d];
#pragma unroll
            for (int o = 16; o; o >>= 1)
                a += __shfl_xor_sync(0xffffffffu, a, o);
            if (lane == 0) g_bias = a;
        }
    }
    else {
        // ---- gather-sum for one (rep, batch): waits only on its own flag --
        const int tb = blockIdx.x - GATHER_BASE;   // 0..15
        const int b  = tb & 7;
        const int r  = tb >> 3;
        const float* rep  = r ? rep2 : rep1;
        const float* repb = rep + (size_t)b * L * D;
        const int target = (int)(g_seq + 1u);

        if (tid == 0) {
            while (g_rb_done[r][b] != target)
                __nanosleep(32);
        }
        __syncthreads();
        __threadfence();   // acquire g_idx

        const int myrow = (lane < K) ? g_idx[r][b][lane] : 0;
        float a0 = 0.f, a1 = 0.f, a2 = 0.f;
#pragma unroll
        for (int t = 0; t < K; ++t) {
            const int row = __shfl_sync(0xffffffffu, myrow, t);
            const float* rp = repb + (size_t)row * D;
            a0 += rp[tid];
            a1 += rp[tid + 512];
            if (tid < 256) a2 += rp[tid + 1024];
        }
        g_s[r][b][tid]       = a0;
        g_s[r][b][tid + 512] = a1;
        if (tid < 256) g_s[r][b][tid + 1024] = a2;
    }
}

// ---------------------------------------------------------------------------
// Kernel B: single block, 512 threads (16 warps). Warp (g,b):
//   g==0: rep1[b,0].u1 + rep2[b,0].u2          (cls branch)
//   g==1: g_s[0][b].v1 + g_s[1][b].v2          (env branch, scaled 1/K)
// out[b] = (cls + env/K + bias + clf biases) / 2. Also bumps g_seq.
// ---------------------------------------------------------------------------
__global__ void __launch_bounds__(512) k_B(
    const float* __restrict__ rep1, const float* __restrict__ rep2,
    const float* __restrict__ clsclf_b, const float* __restrict__ envclf_b,
    float* __restrict__ out)
{
    const int tid  = threadIdx.x;
    const int warp = tid >> 5;
    const int lane = tid & 31;
    const int g = warp >> 3;
    const int b = warp & 7;

    __shared__ float sA[8], sB[8];

    float acc = 0.f;
    if (g == 0) {
        const float* r1 = rep1 + (size_t)b * L * D;   // token 0 row
        const float* r2 = rep2 + (size_t)b * L * D;
#pragma unroll
        for (int it = 0; it < 10; ++it) {
            const int i = lane * 4 + it * 128;
            float4 u1 = add4(*(const float4*)(g_up[0][0] + i),
                             *(const float4*)(g_up[1][0] + i));
            float4 u2 = add4(*(const float4*)(g_up[0][1] + i),
                             *(const float4*)(g_up[1][1] + i));
            acc += dot4(*(const float4*)(r1 + i), u1)
                 + dot4(*(const float4*)(r2 + i), u2);
        }
    } else {
#pragma unroll
        for (int it = 0; it < 10; ++it) {
            const int i = lane * 4 + it * 128;
            float4 v1 = add4(*(const float4*)(g_up[0][2] + i),
                             *(const float4*)(g_up[1][2] + i));
            float4 v2 = add4(*(const float4*)(g_up[0][3] + i),
                             *(const float4*)(g_up[1][3] + i));
            acc += dot4(*(const float4*)(g_s[0][b] + i), v1)
                 + dot4(*(const float4*)(g_s[1][b] + i), v2);
        }
    }
#pragma unroll
    for (int o = 16; o; o >>= 1)
        acc += __shfl_xor_sync(0xffffffffu, acc, o);
    if (lane == 0) {
        if (g == 0) sA[b] = acc; else sB[b] = acc;
    }
    __syncthreads();
    if (tid < 8)
        out[tid] = (sA[tid] + sB[tid] * (1.0f / K)
                    + g_bias + clsclf_b[0] + envclf_b[0]) * 0.5f;
    if (tid == 0) g_seq = g_seq + 1u;   // advance replay sequence
}

// ---------------------------------------------------------------------------
extern "C" void kernel_launch(void* const* d_in, const int* in_sizes, int n_in,
                              void* d_out, int out_size)
{
    const float* rep1     = (const float*)d_in[0];
    const float* rep2     = (const float*)d_in[1];
    const float* attn1    = (const float*)d_in[2];
    const float* attn2    = (const float*)d_in[3];
    const int*   pos      = (const int*)  d_in[4];
    const float* cls_W    = (const float*)d_in[5];
    const float* cls_b    = (const float*)d_in[6];
    const float* env_W    = (const float*)d_in[7];
    const float* env_b    = (const float*)d_in[8];
    const float* clsclf_W = (const float*)d_in[9];
    const float* clsclf_b = (const float*)d_in[10];
    const float* envclf_W = (const float*)d_in[11];
    const float* envclf_b = (const float*)d_in[12];
    const float* cls_c1   = (const float*)d_in[13];
    const float* cls_c2   = (const float*)d_in[14];
    const float* env_c1   = (const float*)d_in[15];
    const float* env_c2   = (const float*)d_in[16];
    float* out = (float*)d_out;

    k_A<<<NB, 512>>>(rep1, rep2, attn1, attn2, pos,
                     cls_W, env_W, cls_b, env_b,
                     clsclf_W, envclf_W,
                     cls_c1, cls_c2, env_c1, env_c2);

    k_B<<<1, 512>>>(rep1, rep2, clsclf_b, envclf_b, out);
}

// round 8
// speedup vs baseline: 1.0125x; 1.0125x over previous
#include <cuda_runtime.h>
#include <cstdint>

#define B 8
#define L 512
#define H 20
#define D 1280
#define K 32

#define MV_BLOCKS   320                      // 16 warps * 320 = 5120 half-rows
#define MV_WARPS    (MV_BLOCKS * 16)         // 5120
#define TOPK_BASE   MV_BLOCKS                // 320
#define GATHER_BASE (MV_BLOCKS + 16)         // 336
#define REDUCE_BID  (MV_BLOCKS + 32)         // 352
#define NB          (REDUCE_BID + 1)         // 353 blocks (>=148: no low-grid throttle)

// Scratch (no allocations allowed in kernel_launch)
__device__ int   g_idx[2][B][K];          // top-K token indices per (rep, batch)
__device__ float g_up[2][4][D];           // j-half partials of u1,u2,v1,v2
__device__ float g_s[2][B][D];            // gather-SUM of selected rep rows
__device__ volatile int g_topk_flag[2][B];// per-(rep,batch) "g_idx ready"
__device__ int   g_mv_done;               // matvec warp completion counter
__device__ int   g_gather_done;           // gather block completion counter

// ---------------------------------------------------------------------------
// Warp-register bitonic sort, 32 u64 keys across lanes, DESCENDING.
// ---------------------------------------------------------------------------
__device__ __forceinline__ unsigned long long warp_sort_desc(
    unsigned long long key, int lane)
{
    unsigned long long v = ~key;
#pragma unroll
    for (int k = 2; k <= 32; k <<= 1) {
#pragma unroll
        for (int j = k >> 1; j > 0; j >>= 1) {
            unsigned long long other = __shfl_xor_sync(0xffffffffu, v, j);
            bool lower = (lane & j) == 0;
            bool up    = (lane & k) == 0;
            unsigned long long mn = (v < other) ? v : other;
            unsigned long long mx = (v < other) ? other : v;
            v = (lower == up) ? mn : mx;
        }
    }
    return ~v;
}

__device__ __forceinline__ float dot4(float4 a, float4 b) {
    return a.x * b.x + a.y * b.y + a.z * b.z + a.w * b.w;
}
__device__ __forceinline__ float4 add4(float4 a, float4 b) {
    return make_float4(a.x + b.x, a.y + b.y, a.z + b.z, a.w + b.w);
}

// ---------------------------------------------------------------------------
// ONE kernel. Block roles by blockIdx.x:
//   [0,320):   dual matvec half-rows -> g_up, per-warp release -> g_mv_done
//   [320,336): top-K per (rep,batch) -> g_idx, sets g_topk_flag[r][b]
//   [336,352): gather-sum per (rep,batch) (spins on own flag) -> g_s
//   352:       bias dot, then spin for all results, final reduce -> out
// ---------------------------------------------------------------------------
__global__ void __launch_bounds__(512) k_all(
    const float* __restrict__ rep1, const float* __restrict__ rep2,
    const float* __restrict__ attn1, const float* __restrict__ attn2,
    const int* __restrict__ pos,
    const float* __restrict__ cls_W, const float* __restrict__ env_W,
    const float* __restrict__ cls_b, const float* __restrict__ env_b,
    const float* __restrict__ clsclf_W, const float* __restrict__ envclf_W,
    const float* __restrict__ clsclf_b, const float* __restrict__ envclf_b,
    const float* __restrict__ cls_c1, const float* __restrict__ cls_c2,
    const float* __restrict__ env_c1, const float* __restrict__ env_c2,
    float* __restrict__ out)
{
    const int tid  = threadIdx.x;
    const int warp = tid >> 5;
    const int lane = tid & 31;

    if (blockIdx.x < MV_BLOCKS) {
        // ---- dual matvec: one warp per HALF row (640 floats) --------------
        const int gw   = blockIdx.x * 16 + warp;   // 0..5119
        const int half = gw & 1;
        const int grow = gw >> 1;                  // 0..2559
        const int mat  = grow >= D;
        const int row  = grow - mat * D;
        const float* W  = mat ? env_W    : cls_W;
        const float* wc = mat ? envclf_W : clsclf_W;
        const float* c1 = mat ? env_c1   : cls_c1;
        const float* c2 = mat ? env_c2   : cls_c2;
        const float* Wr = W + (size_t)row * D;
        const int j0 = half * (D / 2) + lane * 4;

        float4 wv[5];
#pragma unroll
        for (int it = 0; it < 5; ++it)
            wv[it] = *(const float4*)(Wr + j0 + it * 128);

        float a1 = 0.f, a2 = 0.f;
#pragma unroll
        for (int it = 0; it < 5; ++it) {
            const int j = j0 + it * 128;
            float4 wcv = *(const float4*)(wc + j);
            float4 c1v = *(const float4*)(c1 + j);
            float4 c2v = *(const float4*)(c2 + j);
            float sx = wv[it].x * wcv.x, sy = wv[it].y * wcv.y,
                  sz = wv[it].z * wcv.z, sw = wv[it].w * wcv.w;
            a1 += sx * c1v.x + sy * c1v.y + sz * c1v.z + sw * c1v.w;
            a2 += sx * c2v.x + sy * c2v.y + sz * c2v.z + sw * c2v.w;
        }
#pragma unroll
        for (int o = 16; o; o >>= 1) {
            a1 += __shfl_xor_sync(0xffffffffu, a1, o);
            a2 += __shfl_xor_sync(0xffffffffu, a2, o);
        }
        if (lane == 0) {
            g_up[half][mat * 2 + 0][row] = a1;
            g_up[half][mat * 2 + 1][row] = a2;
            __threadfence();                   // release this warp's results
            atomicAdd(&g_mv_done, 1);
        }
    }
    else if (blockIdx.x < GATHER_BASE) {
        // ---- top-K for one (rep, batch) ------------------------------------
        const int tb = blockIdx.x - TOPK_BASE;   // 0..15
        const int b  = tb & 7;
        const int r  = tb >> 3;
        const float* attn = r ? attn2 : attn1;
        const int l = tid;                       // token 0..511
        const int p = pos[b];

        const float* base = attn + ((size_t)b * H) * (size_t)(L * L)
                                 + (size_t)p * L + l;
        float s = 0.f;
#pragma unroll
        for (int h = 0; h < H; ++h)
            s += base[(size_t)h * (L * L)];

        unsigned fb = __float_as_uint(s * (1.0f / H));
        fb = (fb & 0x80000000u) ? ~fb : (fb | 0x80000000u);
        unsigned long long key =
            ((unsigned long long)fb << 32) | (unsigned)(L - 1 - l);

        key = warp_sort_desc(key, lane);

        __shared__ unsigned long long sorted[16][32];
        sorted[warp][lane] = key;
        __syncthreads();

        if (warp == 0) {
            unsigned long long h = (lane < 16) ? sorted[lane][0] : 0ull;
            int ptr = 0;
#pragma unroll
            for (int i = 0; i < K; ++i) {
                unsigned long long m = h;
#pragma unroll
                for (int o = 8; o; o >>= 1) {
                    unsigned long long other = __shfl_xor_sync(0xffffffffu, m, o);
                    if (other > m) m = other;
                }
                m = __shfl_sync(0xffffffffu, m, 0);
                if (h == m) {
                    g_idx[r][b][i] = L - 1 - (int)(m & 0xffffffffu);
                    ++ptr;
                    h = (ptr < 32) ? sorted[lane][ptr] : 0ull;
                }
            }
            __syncwarp();
            if (lane == 0) {
                __threadfence();
                g_topk_flag[r][b] = 1;
            }
        }
    }
    else if (blockIdx.x < REDUCE_BID) {
        // ---- gather-sum for one (rep, batch): waits only on its own flag --
        const int tb = blockIdx.x - GATHER_BASE;   // 0..15
        const int b  = tb & 7;
        const int r  = tb >> 3;
        const float* rep  = r ? rep2 : rep1;
        const float* repb = rep + (size_t)b * L * D;

        if (tid == 0) {
            while (g_topk_flag[r][b] == 0)
                __nanosleep(32);
            __threadfence();                   // acquire g_idx
        }
        __syncthreads();

        const int myrow = g_idx[r][b][lane];
        float a0 = 0.f, a1 = 0.f, a2 = 0.f;
#pragma unroll
        for (int t = 0; t < K; ++t) {
            const int row = __shfl_sync(0xffffffffu, myrow, t);
            const float* rp = repb + (size_t)row * D;
            a0 += rp[tid];
            a1 += rp[tid + 512];
            if (tid < 256) a2 += rp[tid + 1024];
        }
        g_s[r][b][tid]       = a0;
        g_s[r][b][tid + 512] = a1;
        if (tid < 256) g_s[r][b][tid + 1024] = a2;

        __syncthreads();
        if (tid == 0) {
            __threadfence();                   // release g_s
            atomicAdd(&g_gather_done, 1);
        }
    }
    else {
        // ---- dedicated reduce block ----------------------------------------
        __shared__ float sA[8], sB[8], sW[16];

        // (a) bias dot first: depends only on inputs, overlaps everything.
        float bias_acc = 0.f;
        for (int d = tid; d < D; d += 512)
            bias_acc += cls_b[d] * (cls_c1[d] + cls_c2[d]) * clsclf_W[d]
                      + env_b[d] * (env_c1[d] + env_c2[d]) * envclf_W[d];

        // (b) wait for all matvec warps and all gather blocks.
        if (tid == 0) {
            while (atomicAdd(&g_mv_done, 0) < MV_WARPS ||
                   atomicAdd(&g_gather_done, 0) < 16)
                __nanosleep(64);
            __threadfence();                   // acquire g_up / g_s
        }
        __syncthreads();

        // (c) 16 warps: g = warp>>3 (0 cls / 1 env), b = warp&7.
        const int g = warp >> 3;
        const int b = warp & 7;
        float acc = 0.f;
        if (g == 0) {
            const float* r1 = rep1 + (size_t)b * L * D;   // token 0 row
            const float* r2 = rep2 + (size_t)b * L * D;
#pragma unroll
            for (int it = 0; it < 10; ++it) {
                const int i = lane * 4 + it * 128;
                float4 u1 = add4(*(const float4*)(g_up[0][0] + i),
                                 *(const float4*)(g_up[1][0] + i));
                float4 u2 = add4(*(const float4*)(g_up[0][1] + i),
                                 *(const float4*)(g_up[1][1] + i));
                acc += dot4(*(const float4*)(r1 + i), u1)
                     + dot4(*(const float4*)(r2 + i), u2);
            }
        } else {
#pragma unroll
            for (int it = 0; it < 10; ++it) {
                const int i = lane * 4 + it * 128;
                float4 v1 = add4(*(const float4*)(g_up[0][2] + i),
                                 *(const float4*)(g_up[1][2] + i));
                float4 v2 = add4(*(const float4*)(g_up[0][3] + i),
                                 *(const float4*)(g_up[1][3] + i));
                acc += dot4(*(const float4*)(g_s[0][b] + i), v1)
                     + dot4(*(const float4*)(g_s[1][b] + i), v2);
            }
        }
#pragma unroll
        for (int o = 16; o; o >>= 1) {
            acc      += __shfl_xor_sync(0xffffffffu, acc, o);
            bias_acc += __shfl_xor_sync(0xffffffffu, bias_acc, o);
        }
        if (lane == 0) {
            if (g == 0) sA[b] = acc; else sB[b] = acc;
            sW[warp] = bias_acc;
        }
        __syncthreads();

        if (tid < 8) {
            float bias = 0.f;
#pragma unroll
            for (int w = 0; w < 16; ++w) bias += sW[w];
            out[tid] = (sA[tid] + sB[tid] * (1.0f / K)
                        + bias + clsclf_b[0] + envclf_b[0]) * 0.5f;
        }
        if (tid == 0) {
            // reset protocol state for the next graph replay
            g_mv_done = 0;
            g_gather_done = 0;
            for (int i = 0; i < 2 * B; ++i)
                ((volatile int*)&g_topk_flag[0][0])[i] = 0;
            __threadfence();
        }
    }
}

// ---------------------------------------------------------------------------
extern "C" void kernel_launch(void* const* d_in, const int* in_sizes, int n_in,
                              void* d_out, int out_size)
{
    const float* rep1     = (const float*)d_in[0];
    const float* rep2     = (const float*)d_in[1];
    const float* attn1    = (const float*)d_in[2];
    const float* attn2    = (const float*)d_in[3];
    const int*   pos      = (const int*)  d_in[4];
    const float* cls_W    = (const float*)d_in[5];
    const float* cls_b    = (const float*)d_in[6];
    const float* env_W    = (const float*)d_in[7];
    const float* env_b    = (const float*)d_in[8];
    const float* clsclf_W = (const float*)d_in[9];
    const float* clsclf_b = (const float*)d_in[10];
    const float* envclf_W = (const float*)d_in[11];
    const float* envclf_b = (const float*)d_in[12];
    const float* cls_c1   = (const float*)d_in[13];
    const float* cls_c2   = (const float*)d_in[14];
    const float* env_c1   = (const float*)d_in[15];
    const float* env_c2   = (const float*)d_in[16];
    float* out = (float*)d_out;

    k_all<<<NB, 512>>>(rep1, rep2, attn1, attn2, pos,
                       cls_W, env_W, cls_b, env_b,
                       clsclf_W, envclf_W, clsclf_b, envclf_b,
                       cls_c1, cls_c2, env_c1, env_c2, out);
}

// round 9
// speedup vs baseline: 1.1780x; 1.1634x over previous
#include <cuda_runtime.h>
#include <cstdint>

#define B 8
#define L 512
#define H 20
#define D 1280
#define K 32

#define MATVEC_BLOCKS 320   // 16 warps * 320 = 5120 half-rows = 2*2560 rows
#define TOPK_BLOCKS   16    // 2 reps * 8 batches
#define BIAS_BLOCKS   1
#define FUSED_BLOCKS  (MATVEC_BLOCKS + TOPK_BLOCKS + BIAS_BLOCKS)
#define DOT_BLOCKS    132   // 66 tasks * 2 D-halves

// Scratch (no allocations allowed in kernel_launch)
__device__ int   g_idx[2][B][K];    // top-K token indices per (rep, batch)
__device__ float g_up[2][4][D];     // j-half partials of u1,u2,v1,v2
__device__ float g_part[DOT_BLOCKS][B];
__device__ float g_bias;            // batch-independent bias dot
__device__ int   g_ctr;             // k_dots completion counter (self-resetting)

// ---------------------------------------------------------------------------
// Warp-register bitonic sort, 32 u64 keys across lanes, DESCENDING.
// ---------------------------------------------------------------------------
__device__ __forceinline__ unsigned long long warp_sort_desc(
    unsigned long long key, int lane)
{
    unsigned long long v = ~key;
#pragma unroll
    for (int k = 2; k <= 32; k <<= 1) {
#pragma unroll
        for (int j = k >> 1; j > 0; j >>= 1) {
            unsigned long long other = __shfl_xor_sync(0xffffffffu, v, j);
            bool lower = (lane & j) == 0;
            bool up    = (lane & k) == 0;
            unsigned long long mn = (v < other) ? v : other;
            unsigned long long mx = (v < other) ? other : v;
            v = (lower == up) ? mn : mx;
        }
    }
    return ~v;   // lane i holds i-th LARGEST original key
}

// ---------------------------------------------------------------------------
// Kernel 1 (fused): [0,320) dual matvec half-rows; [320,336) top-K; 336 bias.
// Each block triggers programmatic launch completion immediately so the
// dependent k_dots grid can be scheduled while this kernel runs.
// ---------------------------------------------------------------------------
__global__ void __launch_bounds__(512) k_fused(
    const float* __restrict__ attn1, const float* __restrict__ attn2,
    const int* __restrict__ pos,
    const float* __restrict__ cls_W, const float* __restrict__ env_W,
    const float* __restrict__ cls_b, const float* __restrict__ env_b,
    const float* __restrict__ clsclf_W, const float* __restrict__ envclf_W,
    const float* __restrict__ cls_c1, const float* __restrict__ cls_c2,
    const float* __restrict__ env_c1, const float* __restrict__ env_c2)
{
    cudaTriggerProgrammaticLaunchCompletion();

    const int warp = threadIdx.x >> 5;
    const int lane = threadIdx.x & 31;

    if (blockIdx.x < MATVEC_BLOCKS) {
        // --- dual matvec: one warp per HALF row (640 floats, 5 float4/lane)
        const int gw   = blockIdx.x * 16 + warp;   // 0..5119
        const int half = gw & 1;
        const int grow = gw >> 1;                  // 0..2559
        const int mat  = grow >= D;                // 0 = cls, 1 = env
        const int row  = grow - mat * D;
        const float* W  = mat ? env_W    : cls_W;
        const float* wc = mat ? envclf_W : clsclf_W;
        const float* c1 = mat ? env_c1   : cls_c1;
        const float* c2 = mat ? env_c2   : cls_c2;
        const float* Wr = W + (size_t)row * D;
        const int j0 = half * (D / 2) + lane * 4;

        // Front-batch the 5 DRAM loads of the W half-row (max MLP).
        float4 wv[5];
#pragma unroll
        for (int it = 0; it < 5; ++it)
            wv[it] = *(const float4*)(Wr + j0 + it * 128);

        float a1 = 0.f, a2 = 0.f;
#pragma unroll
        for (int it = 0; it < 5; ++it) {
            const int j = j0 + it * 128;
            float4 wcv = *(const float4*)(wc + j);   // L1/L2-hot (5 KB)
            float4 c1v = *(const float4*)(c1 + j);
            float4 c2v = *(const float4*)(c2 + j);
            float sx = wv[it].x * wcv.x, sy = wv[it].y * wcv.y,
                  sz = wv[it].z * wcv.z, sw = wv[it].w * wcv.w;
            a1 += sx * c1v.x + sy * c1v.y + sz * c1v.z + sw * c1v.w;
            a2 += sx * c2v.x + sy * c2v.y + sz * c2v.z + sw * c2v.w;
        }
#pragma unroll
        for (int o = 16; o; o >>= 1) {
            a1 += __shfl_xor_sync(0xffffffffu, a1, o);
            a2 += __shfl_xor_sync(0xffffffffu, a2, o);
        }
        if (lane == 0) {
            g_up[half][mat * 2 + 0][row] = a1;
            g_up[half][mat * 2 + 1][row] = a2;
        }
        return;
    }

    if (blockIdx.x == MATVEC_BLOCKS + TOPK_BLOCKS) {
        // --- bias dot (one warp) ---
        if (warp != 0) return;
        float a = 0.f;
        for (int d = lane; d < D; d += 32)
            a += cls_b[d] * (cls_c1[d] + cls_c2[d]) * clsclf_W[d]
               + env_b[d] * (env_c1[d] + env_c2[d]) * envclf_W[d];
#pragma unroll
        for (int o = 16; o; o >>= 1)
            a += __shfl_xor_sync(0xffffffffu, a, o);
        if (lane == 0) g_bias = a;
        return;
    }

    // --- top-K for one (rep, batch) ---
    const int tb = blockIdx.x - MATVEC_BLOCKS;   // 0..15
    const int b  = tb & 7;
    const int r  = tb >> 3;
    const float* attn = r ? attn2 : attn1;
    const int l = threadIdx.x;                   // token 0..511
    const int p = pos[b];

    const float* base = attn + ((size_t)b * H) * (size_t)(L * L)
                             + (size_t)p * L + l;
    float s = 0.f;
#pragma unroll
    for (int h = 0; h < H; ++h)
        s += base[(size_t)h * (L * L)];

    unsigned fb = __float_as_uint(s * (1.0f / H));
    fb = (fb & 0x80000000u) ? ~fb : (fb | 0x80000000u);
    unsigned long long key =
        ((unsigned long long)fb << 32) | (unsigned)(L - 1 - l);

    key = warp_sort_desc(key, lane);

    __shared__ unsigned long long sorted[16][32];
    sorted[warp][lane] = key;
    __syncthreads();

    if (warp == 0) {
        unsigned long long h = (lane < 16) ? sorted[lane][0] : 0ull;
        int ptr = 0;
#pragma unroll
        for (int i = 0; i < K; ++i) {
            unsigned long long m = h;
#pragma unroll
            for (int o = 8; o; o >>= 1) {
                unsigned long long other = __shfl_xor_sync(0xffffffffu, m, o);
                if (other > m) m = other;
            }
            m = __shfl_sync(0xffffffffu, m, 0);
            if (h == m) {
                g_idx[r][b][i] = L - 1 - (int)(m & 0xffffffffu);
                ++ptr;
                h = (ptr < 32) ? sorted[lane][ptr] : 0ull;
            }
        }
    }
}

// ---------------------------------------------------------------------------
// Kernel 2 (PDL secondary): 132 blocks (task t, D-half hh), 256 threads
// (warp = batch). Dependency-free prologue runs before
// cudaGridDependencySynchronize(); all reads of g_idx/g_up/g_bias come after.
// Last finished block sums all partials and writes out[].
// ---------------------------------------------------------------------------
__global__ void __launch_bounds__(256) k_dots(
    const float* __restrict__ rep1, const float* __restrict__ rep2,
    const float* __restrict__ clsclf_b, const float* __restrict__ envclf_b,
    float* __restrict__ out)
{
    const int t    = blockIdx.x >> 1;    // task 0..65
    const int hh   = blockIdx.x & 1;     // D-half
    const int warp = threadIdx.x >> 5;
    const int lane = threadIdx.x & 31;
    const int b    = warp;               // 8 warps = 8 batches
    const int i0   = hh * (D / 2) + lane * 4;

    // ---- prologue (independent of k_fused): cls-task rep rows prefetch ----
    float4 rv[5];
    bool prefetched = false;
    if (t == 0) {
        const float* row = rep1 + (size_t)b * L * D;
#pragma unroll
        for (int it = 0; it < 5; ++it)
            rv[it] = *(const float4*)(row + i0 + it * 128);
        prefetched = true;
    } else if (t == 1) {
        const float* row = rep2 + (size_t)b * L * D;
#pragma unroll
        for (int it = 0; it < 5; ++it)
            rv[it] = *(const float4*)(row + i0 + it * 128);
        prefetched = true;
    }

    // ---- wait for k_fused results ----
    cudaGridDependencySynchronize();

    int vi;
    float scale;
    if (t == 0)      { vi = 0; scale = 1.f; }
    else if (t == 1) { vi = 1; scale = 1.f; }
    else if (t < 34) { vi = 2; scale = 1.0f / K; }
    else             { vi = 3; scale = 1.0f / K; }

    if (!prefetched) {
        const float* row = (t < 34)
            ? rep1 + ((size_t)b * L + g_idx[0][b][t - 2]) * D
            : rep2 + ((size_t)b * L + g_idx[1][b][t - 34]) * D;
#pragma unroll
        for (int it = 0; it < 5; ++it)
            rv[it] = *(const float4*)(row + i0 + it * 128);
    }

    const float* v0 = g_up[0][vi];
    const float* v1 = g_up[1][vi];

    float a = 0.f;
#pragma unroll
    for (int it = 0; it < 5; ++it) {
        const int i = i0 + it * 128;
        float4 va = *(const float4*)(v0 + i);    // L2-hot (20 KB total)
        float4 vb = *(const float4*)(v1 + i);
        a += rv[it].x * (va.x + vb.x) + rv[it].y * (va.y + vb.y)
           + rv[it].z * (va.z + vb.z) + rv[it].w * (va.w + vb.w);
    }
#pragma unroll
    for (int o = 16; o; o >>= 1)
        a += __shfl_xor_sync(0xffffffffu, a, o);
    if (lane == 0) g_part[blockIdx.x][b] = a * scale;

    // ---- last-block-done final reduction ----
    __syncthreads();
    __shared__ int is_last;
    if (threadIdx.x == 0) {
        __threadfence();
        is_last = (atomicAdd(&g_ctr, 1) == DOT_BLOCKS - 1);
    }
    __syncthreads();
    if (!is_last) return;

    __threadfence();   // acquire all g_part writes
    if (warp < 8) {    // warp b sums its 132 partials
        float s = 0.f;
        for (int tt = lane; tt < DOT_BLOCKS; tt += 32)
            s += g_part[tt][b];
#pragma unroll
        for (int o = 16; o; o >>= 1)
            s += __shfl_xor_sync(0xffffffffu, s, o);
        if (lane == 0)
            out[b] = (s + g_bias + clsclf_b[0] + envclf_b[0]) * 0.5f;
    }
    if (threadIdx.x == 0) g_ctr = 0;   // reset for next graph replay
}

// ---------------------------------------------------------------------------
extern "C" void kernel_launch(void* const* d_in, const int* in_sizes, int n_in,
                              void* d_out, int out_size)
{
    const float* rep1     = (const float*)d_in[0];
    const float* rep2     = (const float*)d_in[1];
    const float* attn1    = (const float*)d_in[2];
    const float* attn2    = (const float*)d_in[3];
    const int*   pos      = (const int*)  d_in[4];
    const float* cls_W    = (const float*)d_in[5];
    const float* cls_b    = (const float*)d_in[6];
    const float* env_W    = (const float*)d_in[7];
    const float* env_b    = (const float*)d_in[8];
    const float* clsclf_W = (const float*)d_in[9];
    const float* clsclf_b = (const float*)d_in[10];
    const float* envclf_W = (const float*)d_in[11];
    const float* envclf_b = (const float*)d_in[12];
    const float* cls_c1   = (const float*)d_in[13];
    const float* cls_c2   = (const float*)d_in[14];
    const float* env_c1   = (const float*)d_in[15];
    const float* env_c2   = (const float*)d_in[16];
    float* out = (float*)d_out;

    k_fused<<<FUSED_BLOCKS, 512>>>(
        attn1, attn2, pos, cls_W, env_W, cls_b, env_b,
        clsclf_W, envclf_W, cls_c1, cls_c2, env_c1, env_c2);

    // PDL launch: k_dots may be scheduled while k_fused is still running;
    // its cudaGridDependencySynchronize() enforces the data dependency.
    cudaLaunchConfig_t cfg = {};
    cfg.gridDim  = dim3(DOT_BLOCKS, 1, 1);
    cfg.blockDim = dim3(256, 1, 1);
    cfg.dynamicSmemBytes = 0;
    cudaLaunchAttribute attrs[1];
    attrs[0].id = cudaLaunchAttributeProgrammaticStreamSerialization;
    attrs[0].val.programmaticStreamSerializationAllowed = 1;
    cfg.attrs = attrs;
    cfg.numAttrs = 1;
    cudaLaunchKernelEx(&cfg, k_dots, rep1, rep2, clsclf_b, envclf_b, out);
}

// round 10
// speedup vs baseline: 1.2339x; 1.0475x over previous
#include <cuda_runtime.h>
#include <cstdint>

#define B 8
#define L 512
#define H 20
#define D 1280
#define K 32

#define MV_BLOCKS   320                      // 16 warps * 320 = 5120 half-rows
#define TOPK_BASE   MV_BLOCKS                // 320
#define GATHER_BASE (MV_BLOCKS + 16)         // 336
#define BIAS_BID    (MV_BLOCKS + 32)         // 352
#define NA          (BIAS_BID + 1)           // 353 blocks
#define NB_B        148                      // kernel B grid (>=148: no throttle)

// Scratch (no allocations allowed in kernel_launch)
__device__ int   g_idx[2][B][K];          // top-K token indices per (rep, batch)
__device__ float g_up[2][4][D];           // j-half partials of u1,u2,v1,v2
__device__ float g_s[2][B][D];            // gather-SUM of selected rep rows
__device__ float g_bias;                  // batch-independent bias dot
__device__ volatile int g_topk_flag[2][B];// per-(rep,batch) "g_idx ready"

// ---------------------------------------------------------------------------
// Warp-register bitonic sort, 32 u64 keys across lanes, DESCENDING.
// ---------------------------------------------------------------------------
__device__ __forceinline__ unsigned long long warp_sort_desc(
    unsigned long long key, int lane)
{
    unsigned long long v = ~key;
#pragma unroll
    for (int k = 2; k <= 32; k <<= 1) {
#pragma unroll
        for (int j = k >> 1; j > 0; j >>= 1) {
            unsigned long long other = __shfl_xor_sync(0xffffffffu, v, j);
            bool lower = (lane & j) == 0;
            bool up    = (lane & k) == 0;
            unsigned long long mn = (v < other) ? v : other;
            unsigned long long mx = (v < other) ? other : v;
            v = (lower == up) ? mn : mx;
        }
    }
    return ~v;
}

__device__ __forceinline__ float dot4(float4 a, float4 b) {
    return a.x * b.x + a.y * b.y + a.z * b.z + a.w * b.w;
}
__device__ __forceinline__ float4 add4(float4 a, float4 b) {
    return make_float4(a.x + b.x, a.y + b.y, a.z + b.z, a.w + b.w);
}

// ---------------------------------------------------------------------------
// Kernel A. Block roles by blockIdx.x:
//   [0,320):   dual matvec half-rows (W read exactly once)     -> g_up
//   [320,336): top-K per (rep,batch), sets g_topk_flag[r][b]   -> g_idx
//   [336,352): gather-sum per (rep,batch), spins on OWN flag   -> g_s
//   352:       bias dot                                        -> g_bias
// No global tail: kernel ends when its slowest block ends.
// ---------------------------------------------------------------------------
__global__ void __launch_bounds__(512) k_A(
    const float* __restrict__ rep1, const float* __restrict__ rep2,
    const float* __restrict__ attn1, const float* __restrict__ attn2,
    const int* __restrict__ pos,
    const float* __restrict__ cls_W, const float* __restrict__ env_W,
    const float* __restrict__ cls_b, const float* __restrict__ env_b,
    const float* __restrict__ clsclf_W, const float* __restrict__ envclf_W,
    const float* __restrict__ cls_c1, const float* __restrict__ cls_c2,
    const float* __restrict__ env_c1, const float* __restrict__ env_c2)
{
    const int tid  = threadIdx.x;
    const int warp = tid >> 5;
    const int lane = tid & 31;

    if (blockIdx.x < MV_BLOCKS) {
        // ---- dual matvec: one warp per HALF row (640 floats) --------------
        const int gw   = blockIdx.x * 16 + warp;   // 0..5119
        const int half = gw & 1;
        const int grow = gw >> 1;                  // 0..2559
        const int mat  = grow >= D;
        const int row  = grow - mat * D;
        const float* W  = mat ? env_W    : cls_W;
        const float* wc = mat ? envclf_W : clsclf_W;
        const float* c1 = mat ? env_c1   : cls_c1;
        const float* c2 = mat ? env_c2   : cls_c2;
        const float* Wr = W + (size_t)row * D;
        const int j0 = half * (D / 2) + lane * 4;

        float4 wv[5];
#pragma unroll
        for (int it = 0; it < 5; ++it)
            wv[it] = *(const float4*)(Wr + j0 + it * 128);

        float a1 = 0.f, a2 = 0.f;
#pragma unroll
        for (int it = 0; it < 5; ++it) {
            const int j = j0 + it * 128;
            float4 wcv = *(const float4*)(wc + j);
            float4 c1v = *(const float4*)(c1 + j);
            float4 c2v = *(const float4*)(c2 + j);
            float sx = wv[it].x * wcv.x, sy = wv[it].y * wcv.y,
                  sz = wv[it].z * wcv.z, sw = wv[it].w * wcv.w;
            a1 += sx * c1v.x + sy * c1v.y + sz * c1v.z + sw * c1v.w;
            a2 += sx * c2v.x + sy * c2v.y + sz * c2v.z + sw * c2v.w;
        }
#pragma unroll
        for (int o = 16; o; o >>= 1) {
            a1 += __shfl_xor_sync(0xffffffffu, a1, o);
            a2 += __shfl_xor_sync(0xffffffffu, a2, o);
        }
        if (lane == 0) {
            g_up[half][mat * 2 + 0][row] = a1;
            g_up[half][mat * 2 + 1][row] = a2;
        }
    }
    else if (blockIdx.x < GATHER_BASE) {
        // ---- top-K for one (rep, batch) ------------------------------------
        const int tb = blockIdx.x - TOPK_BASE;   // 0..15
        const int b  = tb & 7;
        const int r  = tb >> 3;
        const float* attn = r ? attn2 : attn1;
        const int l = tid;                       // token 0..511
        const int p = pos[b];

        const float* base = attn + ((size_t)b * H) * (size_t)(L * L)
                                 + (size_t)p * L + l;
        float s = 0.f;
#pragma unroll
        for (int h = 0; h < H; ++h)
            s += base[(size_t)h * (L * L)];

        unsigned fb = __float_as_uint(s * (1.0f / H));
        fb = (fb & 0x80000000u) ? ~fb : (fb | 0x80000000u);
        unsigned long long key =
            ((unsigned long long)fb << 32) | (unsigned)(L - 1 - l);

        key = warp_sort_desc(key, lane);

        __shared__ unsigned long long sorted[16][32];
        sorted[warp][lane] = key;
        __syncthreads();

        if (warp == 0) {
            unsigned long long h = (lane < 16) ? sorted[lane][0] : 0ull;
            int ptr = 0;
#pragma unroll
            for (int i = 0; i < K; ++i) {
                unsigned long long m = h;
#pragma unroll
                for (int o = 8; o; o >>= 1) {
                    unsigned long long other = __shfl_xor_sync(0xffffffffu, m, o);
                    if (other > m) m = other;
                }
                m = __shfl_sync(0xffffffffu, m, 0);
                if (h == m) {
                    g_idx[r][b][i] = L - 1 - (int)(m & 0xffffffffu);
                    ++ptr;
                    h = (ptr < 32) ? sorted[lane][ptr] : 0ull;
                }
            }
            __syncwarp();
            if (lane == 0) {
                __threadfence();
                g_topk_flag[r][b] = 1;
            }
        }
    }
    else if (blockIdx.x < BIAS_BID) {
        // ---- gather-sum for one (rep, batch): waits only on its own flag --
        const int tb = blockIdx.x - GATHER_BASE;   // 0..15
        const int b  = tb & 7;
        const int r  = tb >> 3;
        const float* rep  = r ? rep2 : rep1;
        const float* repb = rep + (size_t)b * L * D;

        if (tid == 0) {
            while (g_topk_flag[r][b] == 0)
                __nanosleep(32);
            __threadfence();                   // acquire g_idx
        }
        __syncthreads();

        const int myrow = g_idx[r][b][lane];
        float a0 = 0.f, a1 = 0.f, a2 = 0.f;
#pragma unroll
        for (int t = 0; t < K; ++t) {
            const int row = __shfl_sync(0xffffffffu, myrow, t);
            const float* rp = repb + (size_t)row * D;
            a0 += rp[tid];
            a1 += rp[tid + 512];
            if (tid < 256) a2 += rp[tid + 1024];
        }
        g_s[r][b][tid]       = a0;
        g_s[r][b][tid + 512] = a1;
        if (tid < 256) g_s[r][b][tid + 1024] = a2;
    }
    else {
        // ---- bias dot (one warp of block 352) ------------------------------
        if (warp == 0) {
            float a = 0.f;
            for (int d = lane; d < D; d += 32)
                a += cls_b[d] * (cls_c1[d] + cls_c2[d]) * clsclf_W[d]
                   + env_b[d] * (env_c1[d] + env_c2[d]) * envclf_W[d];
#pragma unroll
            for (int o = 16; o; o >>= 1)
                a += __shfl_xor_sync(0xffffffffu, a, o);
            if (lane == 0) g_bias = a;
        }
    }
}

// ---------------------------------------------------------------------------
// Kernel B: 148 blocks (grid >= 148 to dodge the low-grid throttle).
// Blocks 0..7 (one per batch, 512 threads): warps 0-7 cls-chunk dots,
// warps 8-15 env-chunk dots; block-reduce; write out[b].
// Blocks 8..147 exit immediately. Block 0 resets flags for the next replay.
// ---------------------------------------------------------------------------
__global__ void __launch_bounds__(512) k_B(
    const float* __restrict__ rep1, const float* __restrict__ rep2,
    const float* __restrict__ clsclf_b, const float* __restrict__ envclf_b,
    float* __restrict__ out)
{
    const int tid = threadIdx.x;

    if (blockIdx.x == 0 && tid == 0) {
        // reset protocol state for the next graph replay (safe: kernel
        // boundary guarantees kernel A of this replay is fully done, and
        // the next replay's kernel A starts after this kernel completes).
        for (int i = 0; i < 2 * B; ++i)
            ((volatile int*)&g_topk_flag[0][0])[i] = 0;
        __threadfence();
    }
    if (blockIdx.x >= B) return;

    const int b    = blockIdx.x;
    const int warp = tid >> 5;
    const int lane = tid & 31;
    const int g    = warp >> 3;          // 0 = cls pair, 1 = env pair
    const int w    = warp & 7;           // chunk index
    const int base = w * 160;            // 160 floats per chunk

    float acc = 0.f;
    if (g == 0) {
        const float* r1 = rep1 + (size_t)b * L * D;   // token-0 rows
        const float* r2 = rep2 + (size_t)b * L * D;
        for (int j = base + lane * 4; j < base + 160; j += 128) {
            float4 u1 = add4(*(const float4*)(g_up[0][0] + j),
                             *(const float4*)(g_up[1][0] + j));
            float4 u2 = add4(*(const float4*)(g_up[0][1] + j),
                             *(const float4*)(g_up[1][1] + j));
            acc += dot4(*(const float4*)(r1 + j), u1)
                 + dot4(*(const float4*)(r2 + j), u2);
        }
    } else {
        for (int j = base + lane * 4; j < base + 160; j += 128) {
            float4 v1 = add4(*(const float4*)(g_up[0][2] + j),
                             *(const float4*)(g_up[1][2] + j));
            float4 v2 = add4(*(const float4*)(g_up[0][3] + j),
                             *(const float4*)(g_up[1][3] + j));
            acc += dot4(*(const float4*)(g_s[0][b] + j), v1)
                 + dot4(*(const float4*)(g_s[1][b] + j), v2);
        }
    }
#pragma unroll
    for (int o = 16; o; o >>= 1)
        acc += __shfl_xor_sync(0xffffffffu, acc, o);

    __shared__ float red[16];
    if (lane == 0) red[warp] = acc;
    __syncthreads();

    if (tid == 0) {
        float cls = 0.f, env = 0.f;
#pragma unroll
        for (int i = 0; i < 8; ++i)  cls += red[i];
#pragma unroll
        for (int i = 8; i < 16; ++i) env += red[i];
        out[b] = (cls + env * (1.0f / K)
                  + g_bias + clsclf_b[0] + envclf_b[0]) * 0.5f;
    }
}

// ---------------------------------------------------------------------------
extern "C" void kernel_launch(void* const* d_in, const int* in_sizes, int n_in,
                              void* d_out, int out_size)
{
    const float* rep1     = (const float*)d_in[0];
    const float* rep2     = (const float*)d_in[1];
    const float* attn1    = (const float*)d_in[2];
    const float* attn2    = (const float*)d_in[3];
    const int*   pos      = (const int*)  d_in[4];
    const float* cls_W    = (const float*)d_in[5];
    const float* cls_b    = (const float*)d_in[6];
    const float* env_W    = (const float*)d_in[7];
    const float* env_b    = (const float*)d_in[8];
    const float* clsclf_W = (const float*)d_in[9];
    const float* clsclf_b = (const float*)d_in[10];
    const float* envclf_W = (const float*)d_in[11];
    const float* envclf_b = (const float*)d_in[12];
    const float* cls_c1   = (const float*)d_in[13];
    const float* cls_c2   = (const float*)d_in[14];
    const float* env_c1   = (const float*)d_in[15];
    const float* env_c2   = (const float*)d_in[16];
    float* out = (float*)d_out;

    k_A<<<NA, 512>>>(rep1, rep2, attn1, attn2, pos,
                     cls_W, env_W, cls_b, env_b,
                     clsclf_W, envclf_W,
                     cls_c1, cls_c2, env_c1, env_c2);

    k_B<<<NB_B, 512>>>(rep1, rep2, clsclf_b, envclf_b, out);
}